// round 1
// baseline (speedup 1.0000x reference)
#include <cuda_runtime.h>

#define H       1536
#define NH      12
#define NKV     2
#define GQA     6        // NH / NKV
#define HD      128
#define CTX     4096
#define NLAYERS 28
#define NSPLIT  32
#define QKV_ROWS (H + 2*NKV*HD)   // 2048

// ---------------- scratch (device globals; no allocation allowed) ------------
__device__ __align__(16) float g_h[H];            // embedded hidden (residual)
__device__ __align__(16) float g_n[H];            // rmsnorm'd hidden
__device__ __align__(16) float g_qkv[QKV_ROWS];   // q:0..1535, k:1536..1791, v:1792..2047
__device__ __align__(16) float g_q[H];            // rope'd q
__device__ __align__(16) float g_k[NKV*HD];       // rope'd k (current pos)
__device__ float g_m[NH*NSPLIT];
__device__ float g_l[NH*NSPLIT];
__device__ __align__(16) float g_acc[NH*NSPLIT*HD];
__device__ __align__(16) float g_ctx[NH*HD];

__device__ __forceinline__ float warpsum(float v) {
#pragma unroll
    for (int o = 16; o; o >>= 1) v += __shfl_xor_sync(0xffffffffu, v, o);
    return v;
}

// ---------------- kernel 1: embedding gather + RMSNorm -----------------------
__global__ void k_embed_rms(const int* __restrict__ ids,
                            const float* __restrict__ embed_w,
                            const float* __restrict__ ln_w) {
    const int tok = ids[0];
    const float* row = embed_w + (size_t)tok * H;
    float hv[3];
    float ss = 0.f;
    int c = 0;
    for (int j = threadIdx.x; j < H; j += 512, c++) {
        hv[c] = row[j];
        ss += hv[c] * hv[c];
    }
    __shared__ float red[16];
    ss = warpsum(ss);
    if ((threadIdx.x & 31) == 0) red[threadIdx.x >> 5] = ss;
    __syncthreads();
    if (threadIdx.x < 32) {
        float v = (threadIdx.x < 16) ? red[threadIdx.x] : 0.f;
        v = warpsum(v);
        if (threadIdx.x == 0) red[0] = rsqrtf(v / (float)H + 1e-6f);
    }
    __syncthreads();
    const float inv = red[0];
    c = 0;
    for (int j = threadIdx.x; j < H; j += 512, c++) {
        g_h[j] = hv[c];
        g_n[j] = hv[c] * inv * ln_w[j];
    }
}

// ---------------- kernel 2: fused QKV matvec (+bias) -------------------------
// 2048 rows, warp per row, 8 rows per 256-thread block -> 256 blocks
__global__ void __launch_bounds__(256) k_qkv(const float* __restrict__ qw, const float* __restrict__ qb,
                                             const float* __restrict__ kw, const float* __restrict__ kb,
                                             const float* __restrict__ vw, const float* __restrict__ vb) {
    __shared__ float4 sn[H / 4];
    for (int i = threadIdx.x; i < H / 4; i += 256) sn[i] = ((const float4*)g_n)[i];
    __syncthreads();

    const int warp = threadIdx.x >> 5, lane = threadIdx.x & 31;
    const int row = blockIdx.x * 8 + warp;   // 0..2047
    const float* w;
    float b;
    if (row < H)              { w = qw + (size_t)row * H;              b = qb[row]; }
    else if (row < H + NKV*HD){ int r = row - H;          w = kw + (size_t)r * H; b = kb[r]; }
    else                      { int r = row - H - NKV*HD; w = vw + (size_t)r * H; b = vb[r]; }

    const float4* w4 = (const float4*)w;
    float acc = 0.f;
#pragma unroll
    for (int i = 0; i < 12; i++) {
        float4 a = __ldg(&w4[lane + i * 32]);
        float4 n4 = sn[lane + i * 32];
        acc += a.x * n4.x + a.y * n4.y + a.z * n4.z + a.w * n4.w;
    }
    acc = warpsum(acc);
    if (lane == 0) g_qkv[row] = acc + b;
}

// ---------------- kernel 3: RoPE on q (12 heads) and k (2 heads) -------------
__global__ void k_rope(const int* __restrict__ pos_ids) {
    const double p = (double)pos_ids[0];
    for (int idx = threadIdx.x; idx < H + NKV * HD; idx += 256) {
        const int d = idx & 127;
        const int base = idx & ~127;          // rows are 128-aligned
        const int i = d & 63;
        const double inv_freq = exp2(-(double)i / 64.0 * 19.9315685693241740);  // base^{-i/64}
        const double ang = p * inv_freq;
        const float c = (float)cos(ang), s = (float)sin(ang);
        const float x = g_qkv[idx];
        const float other = (d < 64) ? g_qkv[base + d + 64] : g_qkv[base + d - 64];
        const float out = (d < 64) ? (x * c - other * s) : (x * c + other * s);
        if (idx < H) g_q[idx] = out;
        else         g_k[idx - H] = out;
    }
}

// ---------------- kernel 4: flash-decode attention partials ------------------
// grid = (NSPLIT, NKV); 128 threads = 4 warps. Each warp streams K/V vectors and
// dots them against all 6 q-heads of this kv-head (GQA: K/V read exactly once).
__global__ void __launch_bounds__(128) k_attn(const int* __restrict__ pos_ids,
                                              const float* __restrict__ kv_cache) {
    const int cp = pos_ids[0];
    const int kvh = blockIdx.y;
    const int split = blockIdx.x;
    const int nk = cp + 1;                            // positions > cp have mask -1e9 -> exp == 0
    const int chunk = (nk + NSPLIT - 1) / NSPLIT;
    const int t0 = split * chunk;
    const int t1 = min(t0 + chunk, nk);
    const int warp = threadIdx.x >> 5, lane = threadIdx.x & 31;

    float4 q[GQA];
#pragma unroll
    for (int h = 0; h < GQA; h++)
        q[h] = ((const float4*)g_q)[(kvh * GQA + h) * 32 + lane];

    const float4* kc = (const float4*)(kv_cache + (size_t)kvh * CTX * HD);
    const float4* vc = (const float4*)(kv_cache + (size_t)NLAYERS * NKV * CTX * HD + (size_t)kvh * CTX * HD);
    const float4* knew = (const float4*)g_k;
    const float4* vnew = (const float4*)(g_qkv + H + NKV * HD);

    float m[GQA], l[GQA];
    float4 a[GQA];
#pragma unroll
    for (int h = 0; h < GQA; h++) { m[h] = -1e30f; l[h] = 0.f; a[h] = make_float4(0.f, 0.f, 0.f, 0.f); }

    for (int t = t0 + warp; t < t1; t += 4) {
        const bool fresh = (t == cp);
        const float4 kv4 = fresh ? knew[kvh * 32 + lane] : __ldg(&kc[t * 32 + lane]);
        const float4 vv4 = fresh ? vnew[kvh * 32 + lane] : __ldg(&vc[t * 32 + lane]);
#pragma unroll
        for (int h = 0; h < GQA; h++) {
            float d = q[h].x * kv4.x + q[h].y * kv4.y + q[h].z * kv4.z + q[h].w * kv4.w;
            d = warpsum(d) * 0.08838834764831845f;    // 1/sqrt(128)
            const float nm = fmaxf(m[h], d);
            const float sc = __expf(m[h] - nm);
            const float pz = __expf(d - nm);
            l[h] = l[h] * sc + pz;
            a[h].x = a[h].x * sc + pz * vv4.x;
            a[h].y = a[h].y * sc + pz * vv4.y;
            a[h].z = a[h].z * sc + pz * vv4.z;
            a[h].w = a[h].w * sc + pz * vv4.w;
            m[h] = nm;
        }
    }

    __shared__ float  sm[4][GQA], sl[4][GQA];
    __shared__ float4 sa[4][GQA][32];
    if (lane == 0) {
#pragma unroll
        for (int h = 0; h < GQA; h++) { sm[warp][h] = m[h]; sl[warp][h] = l[h]; }
    }
#pragma unroll
    for (int h = 0; h < GQA; h++) sa[warp][h][lane] = a[h];
    __syncthreads();

    if (threadIdx.x < 32) {
#pragma unroll
        for (int h = 0; h < GQA; h++) {
            const float bm = fmaxf(fmaxf(sm[0][h], sm[1][h]), fmaxf(sm[2][h], sm[3][h]));
            float bl = 0.f;
            float4 ba = make_float4(0.f, 0.f, 0.f, 0.f);
#pragma unroll
            for (int w = 0; w < 4; w++) {
                const float e = __expf(sm[w][h] - bm);
                bl += sl[w][h] * e;
                const float4 aw = sa[w][h][lane];
                ba.x += aw.x * e; ba.y += aw.y * e; ba.z += aw.z * e; ba.w += aw.w * e;
            }
            const int qh = kvh * GQA + h;
            if (lane == 0) { g_m[qh * NSPLIT + split] = bm; g_l[qh * NSPLIT + split] = bl; }
            ((float4*)g_acc)[(qh * NSPLIT + split) * 32 + lane] = ba;
        }
    }
}

// ---------------- kernel 5: combine splits -> ctx ----------------------------
__global__ void k_combine() {
    const int qh = blockIdx.x;
    const int lane = threadIdx.x;
    float m = -1e30f;
#pragma unroll
    for (int s = 0; s < NSPLIT; s++) m = fmaxf(m, g_m[qh * NSPLIT + s]);
    float l = 0.f;
    float4 acc = make_float4(0.f, 0.f, 0.f, 0.f);
#pragma unroll
    for (int s = 0; s < NSPLIT; s++) {
        const float e = __expf(g_m[qh * NSPLIT + s] - m);
        l += g_l[qh * NSPLIT + s] * e;
        const float4 a = ((const float4*)g_acc)[(qh * NSPLIT + s) * 32 + lane];
        acc.x += a.x * e; acc.y += a.y * e; acc.z += a.z * e; acc.w += a.w * e;
    }
    const float inv = 1.f / l;
    ((float4*)g_ctx)[qh * 32 + lane] = make_float4(acc.x * inv, acc.y * inv, acc.z * inv, acc.w * inv);
}

// ---------------- kernel 6: O projection + residual --------------------------
__global__ void __launch_bounds__(256) k_oproj(const float* __restrict__ ow, float* __restrict__ out) {
    __shared__ float4 sc[H / 4];
    for (int i = threadIdx.x; i < H / 4; i += 256) sc[i] = ((const float4*)g_ctx)[i];
    __syncthreads();

    const int warp = threadIdx.x >> 5, lane = threadIdx.x & 31;
    const int row = blockIdx.x * 8 + warp;
    const float4* w4 = (const float4*)(ow + (size_t)row * H);
    float acc = 0.f;
#pragma unroll
    for (int i = 0; i < 12; i++) {
        const float4 a = __ldg(&w4[lane + i * 32]);
        const float4 c = sc[lane + i * 32];
        acc += a.x * c.x + a.y * c.y + a.z * c.z + a.w * c.w;
    }
    acc = warpsum(acc);
    if (lane == 0) out[row] = g_h[row] + acc;
}

// ---------------- launch ------------------------------------------------------
extern "C" void kernel_launch(void* const* d_in, const int* in_sizes, int n_in,
                              void* d_out, int out_size) {
    const int*   ids     = (const int*)d_in[0];
    const int*   pos_ids = (const int*)d_in[1];   // == current_pos; avoids unknown scalar dtype at d_in[3]
    const float* embed_w = (const float*)d_in[4];
    const float* ln_w    = (const float*)d_in[5];
    const float* qw      = (const float*)d_in[6];
    const float* qb      = (const float*)d_in[7];
    const float* kw      = (const float*)d_in[8];
    const float* kb      = (const float*)d_in[9];
    const float* vw      = (const float*)d_in[10];
    const float* vb      = (const float*)d_in[11];
    const float* ow      = (const float*)d_in[12];
    const float* kvc     = (const float*)d_in[13];
    float* out = (float*)d_out;

    k_embed_rms<<<1, 512>>>(ids, embed_w, ln_w);
    k_qkv<<<QKV_ROWS / 8, 256>>>(qw, qb, kw, kb, vw, vb);
    k_rope<<<1, 256>>>(pos_ids);
    k_attn<<<dim3(NSPLIT, NKV), 128>>>(pos_ids, kvc);
    k_combine<<<NH, 32>>>();
    k_oproj<<<H / 8, 256>>>(ow, out);
}

// round 2
// speedup vs baseline: 1.8003x; 1.8003x over previous
#include <cuda_runtime.h>

#define H       1536
#define NH      12
#define NKV     2
#define GQA     6        // NH / NKV
#define HD      128
#define CTX     4096
#define NLAYERS 28
#define NSPLIT  128
#define QKV_ROWS (H + 2*NKV*HD)   // 2048

// ---------------- scratch (device globals) ------------------------------------
__device__ __align__(16) float g_qkv[QKV_ROWS];   // q:0..1535, k:1536..1791, v:1792..2047 (pre-rope)
__device__ float g_cos[64];
__device__ float g_sin[64];
__device__ float g_m[NH * NSPLIT];
__device__ float g_l[NH * NSPLIT];
__device__ __align__(16) float g_acc[NH * NSPLIT * HD];
__device__ __align__(16) float g_ctx[NH * HD];

__device__ __forceinline__ float warpsum(float v) {
#pragma unroll
    for (int o = 16; o; o >>= 1) v += __shfl_xor_sync(0xffffffffu, v, o);
    return v;
}
__device__ __forceinline__ float warpmax(float v) {
#pragma unroll
    for (int o = 16; o; o >>= 1) v = fmaxf(v, __shfl_xor_sync(0xffffffffu, v, o));
    return v;
}

// ---------------- kernel 1: embed + RMSNorm + fused QKV matvec + rope tables --
// 2048 rows, warp per row, 8 rows per 256-thread block -> 256 blocks.
__global__ void __launch_bounds__(256) k_qkv(const int* __restrict__ ids,
                                             const int* __restrict__ pos_ids,
                                             const float* __restrict__ embed_w,
                                             const float* __restrict__ ln_w,
                                             const float* __restrict__ qw, const float* __restrict__ qb,
                                             const float* __restrict__ kw, const float* __restrict__ kb,
                                             const float* __restrict__ vw, const float* __restrict__ vb) {
    const int tid = threadIdx.x, warp = tid >> 5, lane = tid & 31;
    const int row = blockIdx.x * 8 + warp;
    const int tok = ids[0];

    // rope angle tables (block 0 only; double precision, written once)
    if (blockIdx.x == 0 && tid < 64) {
        const double p = (double)pos_ids[0];
        const double invf = exp2(-(double)tid * (19.931568569324174 / 64.0)); // 1e6^(-i/64)
        const double ang = p * invf;
        g_cos[tid] = (float)cos(ang);
        g_sin[tid] = (float)sin(ang);
    }

    // weight row prefetch (issued before norm compute to hide DRAM latency)
    const float* w;
    float b;
    if (row < H)                { w = qw + (size_t)row * H;                b = qb[row]; }
    else if (row < H + NKV*HD)  { const int r = row - H;          w = kw + (size_t)r * H; b = kb[r]; }
    else                        { const int r = row - H - NKV*HD; w = vw + (size_t)r * H; b = vb[r]; }
    const float4* w4 = (const float4*)w;
    float4 wr[12];
#pragma unroll
    for (int i = 0; i < 12; i++) wr[i] = __ldg(&w4[lane + i * 32]);

    // embed row + RMSNorm into smem (row is L2-resident across blocks)
    __shared__ float4 sn[H / 4];
    __shared__ float red[9];
    const float4* er  = (const float4*)(embed_w + (size_t)tok * H);
    const float4* lw4 = (const float4*)ln_w;
    float4 e0 = er[tid], l0 = lw4[tid];
    float ss = e0.x * e0.x + e0.y * e0.y + e0.z * e0.z + e0.w * e0.w;
    float4 e1, l1;
    if (tid < H / 4 - 256) {
        e1 = er[tid + 256]; l1 = lw4[tid + 256];
        ss += e1.x * e1.x + e1.y * e1.y + e1.z * e1.z + e1.w * e1.w;
    }
    ss = warpsum(ss);
    if (lane == 0) red[warp] = ss;
    __syncthreads();
    if (tid == 0) {
        float v = 0.f;
#pragma unroll
        for (int i = 0; i < 8; i++) v += red[i];
        red[8] = rsqrtf(v / (float)H + 1e-6f);
    }
    __syncthreads();
    const float inv = red[8];
    sn[tid] = make_float4(e0.x * inv * l0.x, e0.y * inv * l0.y, e0.z * inv * l0.z, e0.w * inv * l0.w);
    if (tid < H / 4 - 256)
        sn[tid + 256] = make_float4(e1.x * inv * l1.x, e1.y * inv * l1.y, e1.z * inv * l1.z, e1.w * inv * l1.w);
    __syncthreads();

    float acc = 0.f;
#pragma unroll
    for (int i = 0; i < 12; i++) {
        const float4 n4 = sn[lane + i * 32];
        acc += wr[i].x * n4.x + wr[i].y * n4.y + wr[i].z * n4.z + wr[i].w * n4.w;
    }
    acc = warpsum(acc);
    if (lane == 0) g_qkv[row] = acc + b;
}

// ---------------- kernel 2: flash-decode attention partials (rope fused) -----
// grid = (NSPLIT, NKV); 256 threads = 8 warps, warp streams timesteps (<=2 rounds).
__global__ void __launch_bounds__(256) k_attn(const int* __restrict__ pos_ids,
                                              const float* __restrict__ kv_cache) {
    const int cp = pos_ids[0];
    const int kvh = blockIdx.y;
    const int split = blockIdx.x;
    const int nk = cp + 1;                            // mask -1e9 beyond cp -> exp == 0
    const int chunk = (nk + NSPLIT - 1) / NSPLIT;
    const int t0 = split * chunk;
    const int t1 = min(t0 + chunk, nk);
    const int warp = threadIdx.x >> 5, lane = threadIdx.x & 31;

    // per-lane rope coefficients (dims 4*lane .. 4*lane+3)
    float c4[4], s4[4];
#pragma unroll
    for (int j = 0; j < 4; j++) {
        const int i = (4 * lane + j) & 63;
        c4[j] = g_cos[i];
        s4[j] = g_sin[i];
    }
    const float sgn = (lane < 16) ? -1.f : 1.f;

    // rope'd q for this kv-head's 6 query heads
    const float4* q4p = (const float4*)g_qkv;
    float4 q[GQA];
#pragma unroll
    for (int h = 0; h < GQA; h++) {
        const float4 x = q4p[(kvh * GQA + h) * 32 + lane];
        const float px = __shfl_xor_sync(0xffffffffu, x.x, 16);
        const float py = __shfl_xor_sync(0xffffffffu, x.y, 16);
        const float pz = __shfl_xor_sync(0xffffffffu, x.z, 16);
        const float pw = __shfl_xor_sync(0xffffffffu, x.w, 16);
        q[h].x = x.x * c4[0] + sgn * px * s4[0];
        q[h].y = x.y * c4[1] + sgn * py * s4[1];
        q[h].z = x.z * c4[2] + sgn * pz * s4[2];
        q[h].w = x.w * c4[3] + sgn * pw * s4[3];
    }
    // rope'd fresh k, fresh v (for t == cp)
    float4 kf;
    {
        const float4 x = q4p[H / 4 + kvh * 32 + lane];
        const float px = __shfl_xor_sync(0xffffffffu, x.x, 16);
        const float py = __shfl_xor_sync(0xffffffffu, x.y, 16);
        const float pz = __shfl_xor_sync(0xffffffffu, x.z, 16);
        const float pw = __shfl_xor_sync(0xffffffffu, x.w, 16);
        kf.x = x.x * c4[0] + sgn * px * s4[0];
        kf.y = x.y * c4[1] + sgn * py * s4[1];
        kf.z = x.z * c4[2] + sgn * pz * s4[2];
        kf.w = x.w * c4[3] + sgn * pw * s4[3];
    }
    const float4 vf = q4p[(H + NKV * HD) / 4 + kvh * 32 + lane];

    const float4* kc = (const float4*)(kv_cache + (size_t)kvh * CTX * HD);
    const float4* vc = (const float4*)(kv_cache + (size_t)NLAYERS * NKV * CTX * HD + (size_t)kvh * CTX * HD);

    float m[GQA], l[GQA];
    float4 a[GQA];
#pragma unroll
    for (int h = 0; h < GQA; h++) { m[h] = -1e30f; l[h] = 0.f; a[h] = make_float4(0.f, 0.f, 0.f, 0.f); }

    // software-pipelined timestep loop (t += 8 warps)
    int t = t0 + warp;
    float4 kcur, vcur;
    if (t < t1) {
        if (t == cp) { kcur = kf; vcur = vf; }
        else         { kcur = __ldg(&kc[t * 32 + lane]); vcur = __ldg(&vc[t * 32 + lane]); }
    }
    while (t < t1) {
        const int tn = t + 8;
        float4 knx, vnx;
        if (tn < t1) {
            if (tn == cp) { knx = kf; vnx = vf; }
            else          { knx = __ldg(&kc[tn * 32 + lane]); vnx = __ldg(&vc[tn * 32 + lane]); }
        }
#pragma unroll
        for (int h = 0; h < GQA; h++) {
            float d = q[h].x * kcur.x + q[h].y * kcur.y + q[h].z * kcur.z + q[h].w * kcur.w;
            d = warpsum(d) * 0.08838834764831845f;   // 1/sqrt(128)
            const float nm = fmaxf(m[h], d);
            const float sc = __expf(m[h] - nm);
            const float pz = __expf(d - nm);
            l[h] = l[h] * sc + pz;
            a[h].x = a[h].x * sc + pz * vcur.x;
            a[h].y = a[h].y * sc + pz * vcur.y;
            a[h].z = a[h].z * sc + pz * vcur.z;
            a[h].w = a[h].w * sc + pz * vcur.w;
            m[h] = nm;
        }
        kcur = knx; vcur = vnx;
        t = tn;
    }

    __shared__ float  sm[8][GQA], sl[8][GQA];
    __shared__ float4 sa[8][GQA][32];
    if (lane == 0) {
#pragma unroll
        for (int h = 0; h < GQA; h++) { sm[warp][h] = m[h]; sl[warp][h] = l[h]; }
    }
#pragma unroll
    for (int h = 0; h < GQA; h++) sa[warp][h][lane] = a[h];
    __syncthreads();

    if (warp < GQA) {
        const int h = warp;
        float bm = -1e30f;
#pragma unroll
        for (int w = 0; w < 8; w++) bm = fmaxf(bm, sm[w][h]);
        float bl = 0.f;
        float4 ba = make_float4(0.f, 0.f, 0.f, 0.f);
#pragma unroll
        for (int w = 0; w < 8; w++) {
            const float e = __expf(sm[w][h] - bm);
            bl += sl[w][h] * e;
            const float4 aw = sa[w][h][lane];
            ba.x += aw.x * e; ba.y += aw.y * e; ba.z += aw.z * e; ba.w += aw.w * e;
        }
        const int qh = kvh * GQA + h;
        if (lane == 0) { g_m[qh * NSPLIT + split] = bm; g_l[qh * NSPLIT + split] = bl; }
        ((float4*)g_acc)[(qh * NSPLIT + split) * 32 + lane] = ba;
    }
}

// ---------------- kernel 3: combine splits -> ctx -----------------------------
// grid = NH blocks, 128 threads (== NSPLIT). Thread s owns split s for phases 1-2,
// then thread d owns output dim d for phase 3 (coalesced g_acc reads).
__global__ void __launch_bounds__(128) k_combine() {
    const int qh = blockIdx.x;
    const int tid = threadIdx.x, warp = tid >> 5, lane = tid & 31;
    __shared__ float se[NSPLIT];
    __shared__ float rm[4], rl[4];

    const float ms = g_m[qh * NSPLIT + tid];
    float wm = warpmax(ms);
    if (lane == 0) rm[warp] = wm;
    __syncthreads();
    const float M = fmaxf(fmaxf(rm[0], rm[1]), fmaxf(rm[2], rm[3]));
    const float e = __expf(ms - M);
    se[tid] = e;
    float le = g_l[qh * NSPLIT + tid] * e;
    le = warpsum(le);
    if (lane == 0) rl[warp] = le;
    __syncthreads();
    const float invL = 1.f / (rl[0] + rl[1] + rl[2] + rl[3]);

    // phase 3: thread d accumulates over splits (warp reads are coalesced in d)
    const float* accp = g_acc + (size_t)qh * NSPLIT * HD + tid;
    float s = 0.f;
#pragma unroll 4
    for (int sp = 0; sp < NSPLIT; sp++) s += se[sp] * __ldg(&accp[sp * HD]);
    g_ctx[qh * HD + tid] = s * invL;
}

// ---------------- kernel 4: O projection + residual ---------------------------
__global__ void __launch_bounds__(256) k_oproj(const int* __restrict__ ids,
                                               const float* __restrict__ embed_w,
                                               const float* __restrict__ ow,
                                               float* __restrict__ out) {
    const int tid = threadIdx.x, warp = tid >> 5, lane = tid & 31;
    const int row = blockIdx.x * 8 + warp;

    // prefetch weight row before the smem barrier
    const float4* w4 = (const float4*)(ow + (size_t)row * H);
    float4 wr[12];
#pragma unroll
    for (int i = 0; i < 12; i++) wr[i] = __ldg(&w4[lane + i * 32]);

    __shared__ float4 sc[H / 4];
    for (int i = tid; i < H / 4; i += 256) sc[i] = ((const float4*)g_ctx)[i];
    __syncthreads();

    float acc = 0.f;
#pragma unroll
    for (int i = 0; i < 12; i++) {
        const float4 c = sc[lane + i * 32];
        acc += wr[i].x * c.x + wr[i].y * c.y + wr[i].z * c.z + wr[i].w * c.w;
    }
    acc = warpsum(acc);
    if (lane == 0) out[row] = embed_w[(size_t)ids[0] * H + row] + acc;
}

// ---------------- launch --------------------------------------------------------
extern "C" void kernel_launch(void* const* d_in, const int* in_sizes, int n_in,
                              void* d_out, int out_size) {
    const int*   ids     = (const int*)d_in[0];
    const int*   pos_ids = (const int*)d_in[1];
    const float* embed_w = (const float*)d_in[4];
    const float* ln_w    = (const float*)d_in[5];
    const float* qw      = (const float*)d_in[6];
    const float* qb      = (const float*)d_in[7];
    const float* kw      = (const float*)d_in[8];
    const float* kb      = (const float*)d_in[9];
    const float* vw      = (const float*)d_in[10];
    const float* vb      = (const float*)d_in[11];
    const float* ow      = (const float*)d_in[12];
    const float* kvc     = (const float*)d_in[13];
    float* out = (float*)d_out;

    k_qkv<<<QKV_ROWS / 8, 256>>>(ids, pos_ids, embed_w, ln_w, qw, qb, kw, kb, vw, vb);
    k_attn<<<dim3(NSPLIT, NKV), 256>>>(pos_ids, kvc);
    k_combine<<<NH, 128>>>();
    k_oproj<<<H / 8, 256>>>(ids, embed_w, ow, out);
}

// round 3
// speedup vs baseline: 1.8186x; 1.0102x over previous
#include <cuda_runtime.h>

#define H       1536
#define NH      12
#define NKV     2
#define GQA     6        // NH / NKV
#define HD      128
#define CTX     4096
#define NLAYERS 28
#define NSPLIT  128
#define QKV_ROWS (H + 2*NKV*HD)   // 2048

// ---------------- scratch (device globals) ------------------------------------
__device__ __align__(16) float g_qkv[QKV_ROWS];   // q:0..1535, k:1536..1791, v:1792..2047 (pre-rope)
__device__ float g_cos[64];
__device__ float g_sin[64];
__device__ float g_m[NH * NSPLIT];
__device__ float g_l[NH * NSPLIT];
__device__ __align__(16) float g_acc[NH * NSPLIT * HD];
__device__ __align__(16) float g_ctx[NH * HD];

__device__ __forceinline__ float warpsum(float v) {
#pragma unroll
    for (int o = 16; o; o >>= 1) v += __shfl_xor_sync(0xffffffffu, v, o);
    return v;
}
__device__ __forceinline__ float warpmax(float v) {
#pragma unroll
    for (int o = 16; o; o >>= 1) v = fmaxf(v, __shfl_xor_sync(0xffffffffu, v, o));
    return v;
}

// ---------------- kernel 1: embed + RMSNorm + fused QKV matvec + rope tables --
// 512 blocks x 256 thr. Block = 4 rows; each row computed by 2 warps (half cols
// each, 6 float4 per lane) -> 4096 warps total keep the full weight read in flight.
__global__ void __launch_bounds__(256) k_qkv(const int* __restrict__ ids,
                                             const int* __restrict__ pos_ids,
                                             const float* __restrict__ embed_w,
                                             const float* __restrict__ ln_w,
                                             const float* __restrict__ qw, const float* __restrict__ qb,
                                             const float* __restrict__ kw, const float* __restrict__ kb,
                                             const float* __restrict__ vw, const float* __restrict__ vb) {
    const int tid = threadIdx.x, warp = tid >> 5, lane = tid & 31;
    const int row = blockIdx.x * 4 + (warp >> 1);
    const int half = warp & 1;
    const int tok = ids[0];

    // rope angle tables (block 0 only; double precision, written once)
    if (blockIdx.x == 0 && tid < 64) {
        const double p = (double)pos_ids[0];
        const double invf = exp2(-(double)tid * (19.931568569324174 / 64.0)); // 1e6^(-i/64)
        const double ang = p * invf;
        g_cos[tid] = (float)cos(ang);
        g_sin[tid] = (float)sin(ang);
    }

    // weight half-row prefetch (issued before norm compute to hide DRAM latency)
    const float* w;
    float b;
    if (row < H)                { w = qw + (size_t)row * H;                b = qb[row]; }
    else if (row < H + NKV*HD)  { const int r = row - H;          w = kw + (size_t)r * H; b = kb[r]; }
    else                        { const int r = row - H - NKV*HD; w = vw + (size_t)r * H; b = vb[r]; }
    const float4* w4 = (const float4*)w + half * 192;   // 192 float4 = 768 cols per half
    float4 wr[6];
#pragma unroll
    for (int i = 0; i < 6; i++) wr[i] = __ldg(&w4[lane + i * 32]);

    // embed row + RMSNorm into smem
    __shared__ float4 sn[H / 4];
    __shared__ float red[9];
    __shared__ float sp[8], sb[4];
    const float4* er  = (const float4*)(embed_w + (size_t)tok * H);
    const float4* lw4 = (const float4*)ln_w;
    float4 e0 = er[tid], l0 = lw4[tid];
    float ss = e0.x * e0.x + e0.y * e0.y + e0.z * e0.z + e0.w * e0.w;
    float4 e1, l1;
    if (tid < H / 4 - 256) {
        e1 = er[tid + 256]; l1 = lw4[tid + 256];
        ss += e1.x * e1.x + e1.y * e1.y + e1.z * e1.z + e1.w * e1.w;
    }
    ss = warpsum(ss);
    if (lane == 0) red[warp] = ss;
    if (lane == 0 && half == 0) sb[warp >> 1] = b;
    __syncthreads();
    if (tid == 0) {
        float v = 0.f;
#pragma unroll
        for (int i = 0; i < 8; i++) v += red[i];
        red[8] = rsqrtf(v / (float)H + 1e-6f);
    }
    __syncthreads();
    const float inv = red[8];
    sn[tid] = make_float4(e0.x * inv * l0.x, e0.y * inv * l0.y, e0.z * inv * l0.z, e0.w * inv * l0.w);
    if (tid < H / 4 - 256)
        sn[tid + 256] = make_float4(e1.x * inv * l1.x, e1.y * inv * l1.y, e1.z * inv * l1.z, e1.w * inv * l1.w);
    __syncthreads();

    float acc = 0.f;
#pragma unroll
    for (int i = 0; i < 6; i++) {
        const float4 n4 = sn[half * 192 + lane + i * 32];
        acc += wr[i].x * n4.x + wr[i].y * n4.y + wr[i].z * n4.z + wr[i].w * n4.w;
    }
    acc = warpsum(acc);
    if (lane == 0) sp[warp] = acc;
    __syncthreads();
    if (tid < 4) g_qkv[blockIdx.x * 4 + tid] = sp[2 * tid] + sp[2 * tid + 1] + sb[tid];
}

// ---------------- kernel 2: flash-decode attention partials (rope fused) -----
// grid = (NSPLIT, NKV), 512 threads = 16 warps. chunk = ceil(1235/128) = 10, so
// each warp handles AT MOST ONE timestep: online softmax degenerates to m=d,l=1.
__global__ void __launch_bounds__(512) k_attn(const int* __restrict__ pos_ids,
                                              const float* __restrict__ kv_cache) {
    const int cp = pos_ids[0];
    const int kvh = blockIdx.y;
    const int split = blockIdx.x;
    const int nk = cp + 1;                            // mask -1e9 beyond cp -> exp == 0
    const int chunk = (nk + NSPLIT - 1) / NSPLIT;
    const int t0 = split * chunk;
    const int t1 = min(t0 + chunk, nk);
    const int warp = threadIdx.x >> 5, lane = threadIdx.x & 31;
    const int t = t0 + warp;
    const bool valid = t < t1;

    // issue K/V load first (longest latency)
    float4 kcur = make_float4(0.f, 0.f, 0.f, 0.f);
    float4 vcur = make_float4(0.f, 0.f, 0.f, 0.f);
    const float4* kc = (const float4*)(kv_cache + (size_t)kvh * CTX * HD);
    const float4* vc = (const float4*)(kv_cache + (size_t)NLAYERS * NKV * CTX * HD + (size_t)kvh * CTX * HD);
    const float4* q4p = (const float4*)g_qkv;
    const bool fresh = (t == cp);
    if (valid && !fresh) {
        kcur = __ldg(&kc[t * 32 + lane]);
        vcur = __ldg(&vc[t * 32 + lane]);
    }

    // per-lane rope coefficients (dims 4*lane .. 4*lane+3)
    float c4[4], s4[4];
#pragma unroll
    for (int j = 0; j < 4; j++) {
        const int i = (4 * lane + j) & 63;
        c4[j] = g_cos[i];
        s4[j] = g_sin[i];
    }
    const float sgn = (lane < 16) ? -1.f : 1.f;

    // rope'd q for this kv-head's 6 query heads
    float4 q[GQA];
#pragma unroll
    for (int h = 0; h < GQA; h++) {
        const float4 x = q4p[(kvh * GQA + h) * 32 + lane];
        const float px = __shfl_xor_sync(0xffffffffu, x.x, 16);
        const float py = __shfl_xor_sync(0xffffffffu, x.y, 16);
        const float pz = __shfl_xor_sync(0xffffffffu, x.z, 16);
        const float pw = __shfl_xor_sync(0xffffffffu, x.w, 16);
        q[h].x = x.x * c4[0] + sgn * px * s4[0];
        q[h].y = x.y * c4[1] + sgn * py * s4[1];
        q[h].z = x.z * c4[2] + sgn * pz * s4[2];
        q[h].w = x.w * c4[3] + sgn * pw * s4[3];
    }
    if (valid && fresh) {
        // fresh k (rope'd) and fresh v for t == cp
        const float4 x = q4p[H / 4 + kvh * 32 + lane];
        const float px = __shfl_xor_sync(0xffffffffu, x.x, 16);
        const float py = __shfl_xor_sync(0xffffffffu, x.y, 16);
        const float pz = __shfl_xor_sync(0xffffffffu, x.z, 16);
        const float pw = __shfl_xor_sync(0xffffffffu, x.w, 16);
        kcur.x = x.x * c4[0] + sgn * px * s4[0];
        kcur.y = x.y * c4[1] + sgn * py * s4[1];
        kcur.z = x.z * c4[2] + sgn * pz * s4[2];
        kcur.w = x.w * c4[3] + sgn * pw * s4[3];
        vcur = q4p[(H + NKV * HD) / 4 + kvh * 32 + lane];
    }

    // per-head score for this warp's single timestep
    __shared__ float  sm[16][GQA];
    __shared__ float4 sv[16][32];
    float m[GQA];
#pragma unroll
    for (int h = 0; h < GQA; h++) {
        float d = q[h].x * kcur.x + q[h].y * kcur.y + q[h].z * kcur.z + q[h].w * kcur.w;
        d = warpsum(d) * 0.08838834764831845f;   // 1/sqrt(128)
        m[h] = valid ? d : -1e30f;
    }
    if (lane == 0) {
#pragma unroll
        for (int h = 0; h < GQA; h++) sm[warp][h] = m[h];
    }
    sv[warp][lane] = vcur;
    __syncthreads();

    // warps 0..5 reduce across the 16 timesteps for head h = warp
    if (warp < GQA) {
        const int h = warp;
        float bm = -1e30f;
#pragma unroll
        for (int w = 0; w < 16; w++) bm = fmaxf(bm, sm[w][h]);
        float bl = 0.f;
        float4 ba = make_float4(0.f, 0.f, 0.f, 0.f);
#pragma unroll
        for (int w = 0; w < 16; w++) {
            const float e = __expf(sm[w][h] - bm);
            bl += e;
            const float4 vw4 = sv[w][lane];
            ba.x += vw4.x * e; ba.y += vw4.y * e; ba.z += vw4.z * e; ba.w += vw4.w * e;
        }
        const int qh = kvh * GQA + h;
        if (lane == 0) { g_m[qh * NSPLIT + split] = bm; g_l[qh * NSPLIT + split] = bl; }
        ((float4*)g_acc)[(qh * NSPLIT + split) * 32 + lane] = ba;
    }
}

// ---------------- kernel 3: combine splits -> ctx -----------------------------
__global__ void __launch_bounds__(128) k_combine() {
    const int qh = blockIdx.x;
    const int tid = threadIdx.x, warp = tid >> 5, lane = tid & 31;
    __shared__ float se[NSPLIT];
    __shared__ float rm[4], rl[4];

    const float ms = g_m[qh * NSPLIT + tid];
    float wm = warpmax(ms);
    if (lane == 0) rm[warp] = wm;
    __syncthreads();
    const float M = fmaxf(fmaxf(rm[0], rm[1]), fmaxf(rm[2], rm[3]));
    const float e = __expf(ms - M);
    se[tid] = e;
    float le = g_l[qh * NSPLIT + tid] * e;
    le = warpsum(le);
    if (lane == 0) rl[warp] = le;
    __syncthreads();
    const float invL = 1.f / (rl[0] + rl[1] + rl[2] + rl[3]);

    // thread d accumulates over splits (coalesced in d)
    const float* accp = g_acc + (size_t)qh * NSPLIT * HD + tid;
    float s = 0.f;
#pragma unroll 4
    for (int sp = 0; sp < NSPLIT; sp++) s += se[sp] * __ldg(&accp[sp * HD]);
    g_ctx[qh * HD + tid] = s * invL;
}

// ---------------- kernel 4: O projection + residual ---------------------------
// 384 blocks x 256 thr; 4 rows/block, 2 warps per row (6 float4 per lane).
__global__ void __launch_bounds__(256) k_oproj(const int* __restrict__ ids,
                                               const float* __restrict__ embed_w,
                                               const float* __restrict__ ow,
                                               float* __restrict__ out) {
    const int tid = threadIdx.x, warp = tid >> 5, lane = tid & 31;
    const int row = blockIdx.x * 4 + (warp >> 1);
    const int half = warp & 1;

    // prefetch weight half-row before the smem barrier
    const float4* w4 = (const float4*)(ow + (size_t)row * H) + half * 192;
    float4 wr[6];
#pragma unroll
    for (int i = 0; i < 6; i++) wr[i] = __ldg(&w4[lane + i * 32]);

    __shared__ float4 sc[H / 4];
    __shared__ float sp[8];
    for (int i = tid; i < H / 4; i += 256) sc[i] = ((const float4*)g_ctx)[i];
    __syncthreads();

    float acc = 0.f;
#pragma unroll
    for (int i = 0; i < 6; i++) {
        const float4 c = sc[half * 192 + lane + i * 32];
        acc += wr[i].x * c.x + wr[i].y * c.y + wr[i].z * c.z + wr[i].w * c.w;
    }
    acc = warpsum(acc);
    if (lane == 0) sp[warp] = acc;
    __syncthreads();
    if (tid < 4) {
        const int r = blockIdx.x * 4 + tid;
        out[r] = embed_w[(size_t)ids[0] * H + r] + sp[2 * tid] + sp[2 * tid + 1];
    }
}

// ---------------- launch --------------------------------------------------------
extern "C" void kernel_launch(void* const* d_in, const int* in_sizes, int n_in,
                              void* d_out, int out_size) {
    const int*   ids     = (const int*)d_in[0];
    const int*   pos_ids = (const int*)d_in[1];
    const float* embed_w = (const float*)d_in[4];
    const float* ln_w    = (const float*)d_in[5];
    const float* qw      = (const float*)d_in[6];
    const float* qb      = (const float*)d_in[7];
    const float* kw      = (const float*)d_in[8];
    const float* kb      = (const float*)d_in[9];
    const float* vw      = (const float*)d_in[10];
    const float* vb      = (const float*)d_in[11];
    const float* ow      = (const float*)d_in[12];
    const float* kvc     = (const float*)d_in[13];
    float* out = (float*)d_out;

    k_qkv<<<QKV_ROWS / 4, 256>>>(ids, pos_ids, embed_w, ln_w, qw, qb, kw, kb, vw, vb);
    k_attn<<<dim3(NSPLIT, NKV), 512>>>(pos_ids, kvc);
    k_combine<<<NH, 128>>>();
    k_oproj<<<H / 4, 256>>>(ids, embed_w, ow, out);
}